// round 13
// baseline (speedup 1.0000x reference)
#include <cuda_runtime.h>
#include <cstdint>

// TVLoss: circular-gradient magnitude mean (== reference's FFT path).
//   gx[i,j] = f[i,j] - f[i,(j+1)%W]
//   gy[i,j] = f[i,j] - f[(i+1)%H,j]
//   out = mean( sqrt(gx^2 + gy^2) )
//
// R13: L2-retention attempt with R4-class residency. Input (100.7MB) fits
// ~126MB L2; every load is ld.global.nc.L2::evict_last.v4.b64 (the only
// width ptxas allows the hint on). 256thr blocks, launch_bounds(256,7)
// (<=36 regs, ~87% occ), KROWS=8 strips -> 1536 blocks (proven work-steal
// granularity), fully static unrolled body, fused last-block reduction.

static constexpr int B = 32, C = 3, H = 512, W = 512;
static constexpr long long TOTAL = (long long)B * C * H * W;   // 25,165,824
static constexpr int PLANES = B * C;               // 96
static constexpr int W8     = W / 8;               // 64 chunks of 8 floats/row
static constexpr int KROWS  = 8;                   // strip height
static constexpr int STRIPS = H / KROWS;           // 64 per plane
static constexpr int NTHR   = 256;                 // 4 strip-workers/block
static constexpr int NBLK   = PLANES * STRIPS / 4; // 1536

__device__ float    g_partials[NBLK];
__device__ unsigned g_count = 0;

__device__ __forceinline__ float fsqrt_approx(float x) {
    float r;
    asm("sqrt.approx.f32 %0, %1;" : "=f"(r) : "f"(x));
    return r;
}

// 32-byte global load (8 floats), non-coherent, L2 evict-last priority.
__device__ __forceinline__ void ldg_el8(const float* __restrict__ p,
                                        float4& a, float4& b) {
    unsigned long long u0, u1, u2, u3;
    asm("ld.global.nc.L2::evict_last.v4.b64 {%0,%1,%2,%3}, [%4];"
        : "=l"(u0), "=l"(u1), "=l"(u2), "=l"(u3) : "l"(p));
    a.x = __uint_as_float((unsigned)u0); a.y = __uint_as_float((unsigned)(u0 >> 32));
    a.z = __uint_as_float((unsigned)u1); a.w = __uint_as_float((unsigned)(u1 >> 32));
    b.x = __uint_as_float((unsigned)u2); b.y = __uint_as_float((unsigned)(u2 >> 32));
    b.z = __uint_as_float((unsigned)u3); b.w = __uint_as_float((unsigned)(u3 >> 32));
}

// 8-element row piece: self (sa,sb), down (da,db), right-neighbor rn.
__device__ __forceinline__ float row_mag8(const float4 sa, const float4 sb,
                                          const float4 da, const float4 db,
                                          const float rn) {
    const float dx0 = sa.x - sa.y, dx1 = sa.y - sa.z, dx2 = sa.z - sa.w;
    const float dx3 = sa.w - sb.x, dx4 = sb.x - sb.y, dx5 = sb.y - sb.z;
    const float dx6 = sb.z - sb.w, dx7 = sb.w - rn;
    const float dy0 = sa.x - da.x, dy1 = sa.y - da.y, dy2 = sa.z - da.z;
    const float dy3 = sa.w - da.w, dy4 = sb.x - db.x, dy5 = sb.y - db.y;
    const float dy6 = sb.z - db.z, dy7 = sb.w - db.w;
    float a  = fsqrt_approx(fmaf(dx0, dx0, dy0 * dy0));
    a += fsqrt_approx(fmaf(dx1, dx1, dy1 * dy1));
    a += fsqrt_approx(fmaf(dx2, dx2, dy2 * dy2));
    a += fsqrt_approx(fmaf(dx3, dx3, dy3 * dy3));
    a += fsqrt_approx(fmaf(dx4, dx4, dy4 * dy4));
    a += fsqrt_approx(fmaf(dx5, dx5, dy5 * dy5));
    a += fsqrt_approx(fmaf(dx6, dx6, dy6 * dy6));
    a += fsqrt_approx(fmaf(dx7, dx7, dy7 * dy7));
    return a;
}

__global__ __launch_bounds__(NTHR, 7)
void tv_fused(const float* __restrict__ inf, float* __restrict__ out) {
    const int tid  = threadIdx.x;
    const int c8   = tid & (W8 - 1);               // 8-float chunk (0..63)
    const int sid  = blockIdx.x * 4 + (tid >> 6);  // global strip id
    const int pl   = sid >> 6;                     // plane (0..95)
    const int st   = sid & (STRIPS - 1);           // strip within plane
    const int row0 = st << 3;                      // first row of strip

    const int planeBase = pl << 18;                // plane * 512*512 floats
    const int lane = tid & 31;
    const int rc8  = (c8 + 1) & (W8 - 1);          // right-neighbor chunk

    float acc = 0.0f;

    float4 sa, sb;
    ldg_el8(&inf[planeBase + (row0 << 9) + (c8 << 3)], sa, sb);

    #pragma unroll
    for (int k = 0; k < KROWS; k++) {
        const int row  = row0 + k;
        const int nrow = (row + 1) & (H - 1);      // circular within plane
        float4 da, db;
        ldg_el8(&inf[planeBase + (nrow << 9) + (c8 << 3)], da, db);

        float rn = __shfl_down_sync(0xFFFFFFFFu, sa.x, 1);
        if (lane == 31)
            rn = __ldg(&inf[planeBase + (row << 9) + (rc8 << 3)]);

        acc += row_mag8(sa, sb, da, db, rn);

        sa = da; sb = db;                          // next row's self = this down
    }

    // ── block reduce (8 warps) ──
    #pragma unroll
    for (int o = 16; o; o >>= 1) acc += __shfl_xor_sync(0xFFFFFFFFu, acc, o);

    __shared__ float smem[NTHR / 32];
    if (lane == 0) smem[tid >> 5] = acc;
    __syncthreads();

    if (tid < 32) {
        float v = (tid < NTHR / 32) ? smem[tid] : 0.0f;
        #pragma unroll
        for (int o = 4; o; o >>= 1) v += __shfl_xor_sync(0xFFFFFFFFu, v, o);
        if (tid == 0) g_partials[blockIdx.x] = v;
    }

    // ── last-block final reduction ──
    __shared__ bool amLast;
    if (tid == 0) {
        __threadfence();
        unsigned prev = atomicAdd(&g_count, 1u);
        amLast = (prev == (unsigned)(NBLK - 1));
    }
    __syncthreads();

    if (amLast) {
        float v = 0.0f;
        for (int i = tid; i < NBLK; i += NTHR) v += g_partials[i];
        #pragma unroll
        for (int o = 16; o; o >>= 1) v += __shfl_xor_sync(0xFFFFFFFFu, v, o);

        __shared__ float sm2[NTHR / 32];
        if (lane == 0) sm2[tid >> 5] = v;
        __syncthreads();
        if (tid < 32) {
            float w = (tid < NTHR / 32) ? sm2[tid] : 0.0f;
            #pragma unroll
            for (int o = 4; o; o >>= 1) w += __shfl_xor_sync(0xFFFFFFFFu, w, o);
            if (tid == 0) {
                out[0] = w / (float)TOTAL;
                g_count = 0;                       // reset for next graph replay
            }
        }
    }
}

extern "C" void kernel_launch(void* const* d_in, const int* in_sizes, int n_in,
                              void* d_out, int out_size) {
    tv_fused<<<NBLK, NTHR>>>((const float*)d_in[0], (float*)d_out);
}

// round 14
// speedup vs baseline: 1.6400x; 1.6400x over previous
#include <cuda_runtime.h>
#include <cstdint>

// TVLoss: circular-gradient magnitude mean (== reference's FFT path).
//   gx[i,j] = f[i,j] - f[i,(j+1)%W]
//   gy[i,j] = f[i,j] - f[(i+1)%H,j]
//   out = mean( sqrt(gx^2 + gy^2) )
//
// R14: R4's proven grid (1536 blocks x 256thr, 2 strips of KROWS=16,
// work-steal, no min-blocks clamp) with ONE change: inner loop unrolled x4
// issuing 4 independent LDG.128 back-to-back (MLP=4/thread) to double
// in-flight bytes -- profiles show we're latency-bound (HBM 4.1/8 TB/s,
// issue only 37%), not bandwidth-bound.

static constexpr int B = 32, C = 3, H = 512, W = 512;
static constexpr long long TOTAL = (long long)B * C * H * W;   // 25,165,824
static constexpr int PLANES = B * C;               // 96
static constexpr int W4     = W / 4;               // 128 float4/row
static constexpr int KROWS  = 16;                  // strip height
static constexpr int STRIPS = H / KROWS;           // 32 per plane
static constexpr int NTHR   = 256;                 // 2 strips/block
static constexpr int NBLK   = PLANES * STRIPS / 2; // 1536

__device__ float    g_partials[NBLK];
__device__ unsigned g_count = 0;

__device__ __forceinline__ float fsqrt_approx(float x) {
    float r;
    asm("sqrt.approx.f32 %0, %1;" : "=f"(r) : "f"(x));
    return r;
}

// One row: self s, down d, right-neighbor scalar rn.
__device__ __forceinline__ float row_mag(const float4 s, const float4 d, const float rn) {
    const float dx0 = s.x - s.y, dx1 = s.y - s.z;
    const float dx2 = s.z - s.w, dx3 = s.w - rn;
    const float dy0 = s.x - d.x, dy1 = s.y - d.y;
    const float dy2 = s.z - d.z, dy3 = s.w - d.w;
    float a  = fsqrt_approx(fmaf(dx0, dx0, dy0 * dy0));
    a += fsqrt_approx(fmaf(dx1, dx1, dy1 * dy1));
    a += fsqrt_approx(fmaf(dx2, dx2, dy2 * dy2));
    a += fsqrt_approx(fmaf(dx3, dx3, dy3 * dy3));
    return a;
}

__global__ __launch_bounds__(NTHR)
void tv_fused(const float4* __restrict__ in4, float* __restrict__ out) {
    const float* __restrict__ inf = (const float*)in4;

    const int tid  = threadIdx.x;
    const int c4   = tid & (W4 - 1);               // column (float4 units)
    const int sid  = blockIdx.x * 2 + (tid >> 7);  // global strip id
    const int pl   = sid >> 5;                     // plane (0..95)
    const int st   = sid & (STRIPS - 1);           // strip within plane
    const int row0 = st << 4;                      // first row of strip

    const int planeBase = pl << 16;                // plane * 512 rows * 128 f4
    const int lane = tid & 31;
    const int rc4  = (c4 + 1) & (W4 - 1);          // right-neighbor column

    float acc = 0.0f;

    float4 s = in4[planeBase + (row0 << 7) + c4];

    #pragma unroll
    for (int k = 0; k < KROWS; k += 4) {
        // 4 independent loads, issued back-to-back (MLP=4 per thread)
        const int n1 = (row0 + k + 1) & (H - 1);
        const int n2 = (row0 + k + 2) & (H - 1);
        const int n3 = (row0 + k + 3) & (H - 1);
        const int n4 = (row0 + k + 4) & (H - 1);
        const float4 d1 = in4[planeBase + (n1 << 7) + c4];
        const float4 d2 = in4[planeBase + (n2 << 7) + c4];
        const float4 d3 = in4[planeBase + (n3 << 7) + c4];
        const float4 d4 = in4[planeBase + (n4 << 7) + c4];

        float rn;

        rn = __shfl_down_sync(0xFFFFFFFFu, s.x, 1);
        if (lane == 31) rn = __ldg(&inf[(planeBase << 2) + ((row0 + k) << 9) + (rc4 << 2)]);
        acc += row_mag(s, d1, rn);

        rn = __shfl_down_sync(0xFFFFFFFFu, d1.x, 1);
        if (lane == 31) rn = __ldg(&inf[(planeBase << 2) + ((row0 + k + 1) << 9) + (rc4 << 2)]);
        acc += row_mag(d1, d2, rn);

        rn = __shfl_down_sync(0xFFFFFFFFu, d2.x, 1);
        if (lane == 31) rn = __ldg(&inf[(planeBase << 2) + ((row0 + k + 2) << 9) + (rc4 << 2)]);
        acc += row_mag(d2, d3, rn);

        rn = __shfl_down_sync(0xFFFFFFFFu, d3.x, 1);
        if (lane == 31) rn = __ldg(&inf[(planeBase << 2) + ((row0 + k + 3) << 9) + (rc4 << 2)]);
        acc += row_mag(d3, d4, rn);

        s = d4;
    }

    // ── block reduce (8 warps) ──
    #pragma unroll
    for (int o = 16; o; o >>= 1) acc += __shfl_xor_sync(0xFFFFFFFFu, acc, o);

    __shared__ float smem[NTHR / 32];
    if (lane == 0) smem[tid >> 5] = acc;
    __syncthreads();

    if (tid < 32) {
        float v = (tid < NTHR / 32) ? smem[tid] : 0.0f;
        #pragma unroll
        for (int o = 4; o; o >>= 1) v += __shfl_xor_sync(0xFFFFFFFFu, v, o);
        if (tid == 0) g_partials[blockIdx.x] = v;
    }

    // ── last-block final reduction ──
    __shared__ bool amLast;
    if (tid == 0) {
        __threadfence();
        unsigned prev = atomicAdd(&g_count, 1u);
        amLast = (prev == (unsigned)(NBLK - 1));
    }
    __syncthreads();

    if (amLast) {
        float v = 0.0f;
        for (int i = tid; i < NBLK; i += NTHR) v += g_partials[i];
        #pragma unroll
        for (int o = 16; o; o >>= 1) v += __shfl_xor_sync(0xFFFFFFFFu, v, o);

        __shared__ float sm2[NTHR / 32];
        if (lane == 0) sm2[tid >> 5] = v;
        __syncthreads();
        if (tid < 32) {
            float w = (tid < NTHR / 32) ? sm2[tid] : 0.0f;
            #pragma unroll
            for (int o = 4; o; o >>= 1) w += __shfl_xor_sync(0xFFFFFFFFu, w, o);
            if (tid == 0) {
                out[0] = w / (float)TOTAL;
                g_count = 0;                       // reset for next graph replay
            }
        }
    }
}

extern "C" void kernel_launch(void* const* d_in, const int* in_sizes, int n_in,
                              void* d_out, int out_size) {
    tv_fused<<<NBLK, NTHR>>>((const float4*)d_in[0], (float*)d_out);
}